// round 15
// baseline (speedup 1.0000x reference)
#include <cuda_runtime.h>
#include <cuda_fp16.h>
#include <cstdint>

// ---------------------------------------------------------------------------
// SelfAttention N=4096, D=1024 via mma.sync fp16 (all GEMMs 1-pass)
//   x -> fp16 (also zeros Rsum) ; W^T x3 -> fp16 (1 launch)
//   QKV = x@[Wq^T;Wk^T;Wv^T]  (one GEMM, N=3072; Q,K -> QKV buffer,
//                              V cols written TRANSPOSED into Vt in-epilogue)
//   S-GEMM epilogue: Ps = exp(S/32) fp16, Rsum[row] += partials
//   out = P@V^T / Rsum[row]   (divide in epilogue)
// R15: 512 threads/CTA, 16 warps, 64x32 warp tiles (R3-proven B mapping),
//      ~110 regs/thread -> 4 warps/SMSP latency hiding.
// GEMM loop: 4-stage (48KB/stage), loads for kc+3 issued BEFORE compute,
// CP_WAIT(2), ONE __syncthreads per chunk (R14-proven skeleton).
// ---------------------------------------------------------------------------

#define NTOK 4096
#define DIM  1024
#define QKVLD 3072
#define SOFTMAX_SCALE 0.03125f

#define BM 128
#define BN 256
#define THREADS 512
#define A_T (BM * 128)                 // 16KB
#define B_T (BN * 128)                 // 32KB
#define STG (A_T + B_T)                // 48KB per stage
#define SMEM_G (4 * STG)               // 192KB

// ------------------------------- scratch -----------------------------------
__device__ __align__(256) __half g_xs[NTOK*DIM];
__device__ __align__(256) __half g_Wt[3][DIM*DIM];
__device__ __align__(256) __half g_QKV[NTOK*QKVLD];     // cols: Q|K|(V unused)
__device__ __align__(256) __half g_Vt[DIM*NTOK];
__device__ __align__(256) __half g_Ps[(size_t)NTOK*NTOK];
__device__ __align__(256) float  g_Rsum[NTOK];

// ------------------------------- PTX helpers -------------------------------
__device__ __forceinline__ uint32_t smem_u32(const void* p) {
    uint32_t a;
    asm("{ .reg .u64 t; cvta.to.shared.u64 t, %1; cvt.u32.u64 %0, t; }" : "=r"(a) : "l"(p));
    return a;
}
#define CP_ASYNC16(dst, src) \
    asm volatile("cp.async.cg.shared.global [%0], [%1], 16;\n" :: "r"(dst), "l"(src))
#define CP_COMMIT()  asm volatile("cp.async.commit_group;\n" ::: "memory")
#define CP_WAIT(n)   asm volatile("cp.async.wait_group %0;\n" :: "n"(n) : "memory")

__device__ __forceinline__ void ldmatrix_x4(uint32_t* r, uint32_t addr) {
    asm volatile("ldmatrix.sync.aligned.m8n8.x4.shared.b16 {%0,%1,%2,%3}, [%4];"
                 : "=r"(r[0]), "=r"(r[1]), "=r"(r[2]), "=r"(r[3]) : "r"(addr));
}
__device__ __forceinline__ void mma16816(float* c, const uint32_t* a, const uint32_t* b) {
    asm volatile(
        "mma.sync.aligned.m16n8k16.row.col.f32.f16.f16.f32 "
        "{%0,%1,%2,%3}, {%4,%5,%6,%7}, {%8,%9}, {%0,%1,%2,%3};"
        : "+f"(c[0]), "+f"(c[1]), "+f"(c[2]), "+f"(c[3])
        : "r"(a[0]), "r"(a[1]), "r"(a[2]), "r"(a[3]), "r"(b[0]), "r"(b[1]));
}

// ------------------------- tile loader (cp.async) --------------------------
template <int NROWS>
__device__ __forceinline__ void load_tile(uint32_t dst, const __half* src,
                                          int ld, int tid) {
    const int n16 = NROWS * 8;
#pragma unroll
    for (int i = tid; i < n16; i += THREADS) {
        int r = i >> 3, c = i & 7;
        uint32_t off = (uint32_t)(r * 128) + (uint32_t)((c * 16) ^ ((r & 7) * 16));
        CP_ASYNC16(dst + off, src + (size_t)r * ld + c * 8);
    }
}

// --------------------------- GEMM core (1-pass) ------------------------------
// C = A @ B^T,  A[M,K] ldA, B[N,K] ldB, fp16 inputs, fp32 accum.
// 512 threads, 16 warps (2 wm x 8 wn), warp tile 64x32.
// EPI 3: fp32 out / rowScale[row]                     (PV)
// EPI 4: Ch = exp(acc/32) fp16; atomic row-sum -> Cf  (S + fused softmax)
// EPI 5: bn < 2*DIM: fp16 -> Ch (ldC);  bn >= 2*DIM: transposed fp16 -> Ch2
// Loop: 4-stage, loads for kc+3 issued before compute, CP_WAIT(2), 1 sync/kc.
template <int EPI>
__global__ __launch_bounds__(THREADS, 1)
void gemm_1p(const __half* __restrict__ Ah, const __half* __restrict__ Bh,
             int Kdim, int ldA, int ldB, int ldC,
             float* __restrict__ Cf,
             __half* __restrict__ Ch, __half* __restrict__ Ch2,
             const float* __restrict__ rowScale)
{
    extern __shared__ char smem[];
    const uint32_t sbase = smem_u32(smem);
    const int tid = threadIdx.x;
    const int wid = tid >> 5;
    const int lane = tid & 31;
    const int wm = wid >> 3;       // 0..1  (64-row slab)
    const int wn = wid & 7;        // 0..7  (32-col slab)
    const int bm = blockIdx.y * BM;
    const int bn = blockIdx.x * BN;
    const int NC = Kdim / 64;

    const int aRow  = wm * 64 + (lane & 15);                          // + mi*16
    const int aColb = ((lane >> 4) & 1) * 16;                         // + ks*32
    const int bRow  = wn * 32 + (lane & 7) + ((lane >> 4) & 1) * 8;   // + p*16
    const int bColb = ((lane >> 3) & 1) * 16;                         // + ks*32

    const __half* a_h = Ah + (size_t)bm * ldA;
    const __half* b_h = Bh + (size_t)bn * ldB;

    float acc[4][4][4];
#pragma unroll
    for (int i = 0; i < 4; i++)
#pragma unroll
        for (int j = 0; j < 4; j++)
#pragma unroll
            for (int r = 0; r < 4; r++) acc[i][j][r] = 0.f;

    // prologue: chunks 0,1,2 -> slots 0,1,2
#pragma unroll
    for (int c0 = 0; c0 < 3; c0++) {
        uint32_t sb = sbase + c0 * STG;
        load_tile<BM>(sb,       a_h + c0 * 64, ldA, tid);
        load_tile<BN>(sb + A_T, b_h + c0 * 64, ldB, tid);
        CP_COMMIT();
    }

    for (int kc = 0; kc < NC; kc++) {
        CP_WAIT(2);              // chunk kc complete (kc+1, kc+2 in flight)
        __syncthreads();         // all warps done reading slot (kc+3)&3

        // issue loads for chunk kc+3 BEFORE compute (hidden under MMA)
        if (kc + 3 < NC) {
            uint32_t sb2 = sbase + ((kc + 3) & 3) * STG;
            load_tile<BM>(sb2,       a_h + (kc + 3) * 64, ldA, tid);
            load_tile<BN>(sb2 + A_T, b_h + (kc + 3) * 64, ldB, tid);
        }
        CP_COMMIT();             // always commit (empty groups keep depth exact)

        // compute chunk kc
        const uint32_t sb = sbase + (kc & 3) * STG;
#pragma unroll
        for (int ks = 0; ks < 4; ks++) {
            uint32_t bfr[4][2];
#pragma unroll
            for (int p = 0; p < 2; p++) {
                int r = bRow + p * 16;
                uint32_t off = (uint32_t)(r * 128) +
                               (uint32_t)(((ks * 32) + bColb) ^ ((r & 7) * 16));
                uint32_t t[4];
                ldmatrix_x4(t, sb + A_T + off);
                bfr[2 * p][0] = t[0]; bfr[2 * p][1] = t[1];
                bfr[2 * p + 1][0] = t[2]; bfr[2 * p + 1][1] = t[3];
            }
#pragma unroll
            for (int mi = 0; mi < 4; mi++) {
                int r = aRow + mi * 16;
                uint32_t off = (uint32_t)(r * 128) +
                               (uint32_t)(((ks * 32) + aColb) ^ ((r & 7) * 16));
                uint32_t afr[4];
                ldmatrix_x4(afr, sb + off);
#pragma unroll
                for (int ni = 0; ni < 4; ni++)
                    mma16816(acc[mi][ni], afr, bfr[ni]);
            }
        }
    }

    // ---- epilogue ----
    const int cRowBase = bm + wm * 64 + (lane >> 2);
    const int cColBase = bn + wn * 32 + (lane & 3) * 2;
#pragma unroll
    for (int mi = 0; mi < 4; mi++) {
        const int r0 = cRowBase + mi * 16;
        const int r1 = r0 + 8;
        if (EPI == 5) {
            if (bn < 2 * DIM) {
#pragma unroll
                for (int ni = 0; ni < 4; ni++) {
                    const int col = cColBase + ni * 8;
                    const float* d = acc[mi][ni];
                    __half2 v0, v1;
                    v0.x = __float2half_rn(d[0]); v0.y = __float2half_rn(d[1]);
                    v1.x = __float2half_rn(d[2]); v1.y = __float2half_rn(d[3]);
                    *(__half2*)&Ch[(size_t)r0 * ldC + col] = v0;
                    *(__half2*)&Ch[(size_t)r1 * ldC + col] = v1;
                }
            } else {
                // V block: write transposed into Ch2 = Vt [DIM, NTOK]
#pragma unroll
                for (int ni = 0; ni < 4; ni++) {
                    const int vcol = cColBase - 2 * DIM + ni * 8;
                    const float* d = acc[mi][ni];
                    Ch2[(size_t)(vcol + 0) * NTOK + r0] = __float2half_rn(d[0]);
                    Ch2[(size_t)(vcol + 1) * NTOK + r0] = __float2half_rn(d[1]);
                    Ch2[(size_t)(vcol + 0) * NTOK + r1] = __float2half_rn(d[2]);
                    Ch2[(size_t)(vcol + 1) * NTOK + r1] = __float2half_rn(d[3]);
                }
            }
        } else if (EPI == 3) {
            const float rs0 = 1.0f / rowScale[r0];
            const float rs1 = 1.0f / rowScale[r1];
#pragma unroll
            for (int ni = 0; ni < 4; ni++) {
                const int col = cColBase + ni * 8;
                const float* d = acc[mi][ni];
                float2 v0 = make_float2(d[0] * rs0, d[1] * rs0);
                float2 v1 = make_float2(d[2] * rs1, d[3] * rs1);
                *(float2*)&Cf[(size_t)r0 * ldC + col] = v0;
                *(float2*)&Cf[(size_t)r1 * ldC + col] = v1;
            }
        } else {  // EPI == 4: exp + fp16 store + atomic row-sum
            float s0 = 0.f, s1 = 0.f;
#pragma unroll
            for (int ni = 0; ni < 4; ni++) {
                const int col = cColBase + ni * 8;
                const float* d = acc[mi][ni];
                float e0 = __expf(d[0] * SOFTMAX_SCALE);
                float e1 = __expf(d[1] * SOFTMAX_SCALE);
                float e2 = __expf(d[2] * SOFTMAX_SCALE);
                float e3 = __expf(d[3] * SOFTMAX_SCALE);
                __half2 v0, v1;
                v0.x = __float2half_rn(e0); v0.y = __float2half_rn(e1);
                v1.x = __float2half_rn(e2); v1.y = __float2half_rn(e3);
                *(__half2*)&Ch[(size_t)r0 * ldC + col] = v0;
                *(__half2*)&Ch[(size_t)r1 * ldC + col] = v1;
                s0 += e0 + e1;
                s1 += e2 + e3;
            }
            s0 += __shfl_xor_sync(0xffffffff, s0, 1);
            s0 += __shfl_xor_sync(0xffffffff, s0, 2);
            s1 += __shfl_xor_sync(0xffffffff, s1, 1);
            s1 += __shfl_xor_sync(0xffffffff, s1, 2);
            if ((lane & 3) == 0) {
                atomicAdd(&Cf[r0], s0);
                atomicAdd(&Cf[r1], s1);
            }
        }
    }
}

// ----------------------------- aux kernels ---------------------------------
// x -> single fp16; threads < NTOK also zero Rsum
__global__ __launch_bounds__(256)
void convert_f32h(const float* __restrict__ src, __half* __restrict__ ds,
                  float* __restrict__ rsum, int n4)
{
    int i = blockIdx.x * blockDim.x + threadIdx.x;
    if (i < NTOK) rsum[i] = 0.f;
    if (i >= n4) return;
    float4 v = ((const float4*)src)[i];
    __half2 h0, h1;
    h0.x = __float2half_rn(v.x); h0.y = __float2half_rn(v.y);
    h1.x = __float2half_rn(v.z); h1.y = __float2half_rn(v.w);
    ((__half2*)ds)[i * 2 + 0] = h0;
    ((__half2*)ds)[i * 2 + 1] = h1;
}

// dst[z][C,R] (single fp16) = transpose(srcz[R,C] fp32), z selects Wq/Wk/Wv
__global__ __launch_bounds__(256)
void transpose_w3(const float* __restrict__ s0, const float* __restrict__ s1,
                  const float* __restrict__ s2, __half* __restrict__ dst)
{
    __shared__ float t[32][33];
    const float* src = (blockIdx.z == 0) ? s0 : (blockIdx.z == 1) ? s1 : s2;
    __half* d = dst + (size_t)blockIdx.z * DIM * DIM;
    const int bx = blockIdx.x * 32;
    const int by = blockIdx.y * 32;
    const int x = threadIdx.x, y = threadIdx.y;  // (32, 8)
#pragma unroll
    for (int i = 0; i < 32; i += 8)
        t[y + i][x] = src[(size_t)(by + y + i) * DIM + bx + x];
    __syncthreads();
#pragma unroll
    for (int i = 0; i < 32; i += 8)
        d[(size_t)(bx + y + i) * DIM + by + x] = __float2half_rn(t[x][y + i]);
}

// ------------------------------- driver ------------------------------------
extern "C" void kernel_launch(void* const* d_in, const int* in_sizes, int n_in,
                              void* d_out, int out_size)
{
    const float* x  = (const float*)d_in[0];
    const float* Wq = (const float*)d_in[1];
    const float* Wk = (const float*)d_in[2];
    const float* Wv = (const float*)d_in[3];
    float* out = (float*)d_out;

    __half *xs, *Wt, *QKV, *Vt, *Ps;
    float *Rsum;
    cudaGetSymbolAddress((void**)&xs, g_xs);
    cudaGetSymbolAddress((void**)&Wt, g_Wt);
    cudaGetSymbolAddress((void**)&QKV, g_QKV);
    cudaGetSymbolAddress((void**)&Vt, g_Vt);
    cudaGetSymbolAddress((void**)&Ps, g_Ps);
    cudaGetSymbolAddress((void**)&Rsum, g_Rsum);

    __half* Qs = QKV;                 // cols    0..1023
    __half* Ks = QKV + DIM;           // cols 1024..2047

    cudaFuncSetAttribute(gemm_1p<5>, cudaFuncAttributeMaxDynamicSharedMemorySize, SMEM_G);
    cudaFuncSetAttribute(gemm_1p<4>, cudaFuncAttributeMaxDynamicSharedMemorySize, SMEM_G);
    cudaFuncSetAttribute(gemm_1p<3>, cudaFuncAttributeMaxDynamicSharedMemorySize, SMEM_G);

    // 1. x -> fp16 (+ zero Rsum) ; W^T x3 single fp16 (one launch)
    convert_f32h<<<(NTOK * DIM / 4 + 255) / 256, 256>>>(x, xs, Rsum, NTOK * DIM / 4);
    dim3 tb(32, 8);
    transpose_w3<<<dim3(DIM / 32, DIM / 32, 3), tb>>>(Wq, Wk, Wv, Wt);

    // 2. fused QKV projection (N=3072); V columns written transposed -> Vt
    dim3 blk(THREADS);
    dim3 gQKV(QKVLD / BN, NTOK / BM);  // (12, 32)
    gemm_1p<5><<<gQKV, blk, SMEM_G>>>(xs, Wt, DIM, DIM, DIM, QKVLD,
                                      nullptr, QKV, Vt, nullptr);

    // 3. Ps = exp(K@Q^T / 32), Rsum += row partials   (fused softmax)
    dim3 gS(NTOK / BN, NTOK / BM);     // (16, 32)
    gemm_1p<4><<<gS, blk, SMEM_G>>>(Ks, Qs, DIM, QKVLD, QKVLD, NTOK,
                                    Rsum, Ps, nullptr, nullptr);

    // 4. out = (P @ V^T) / Rsum[row]
    dim3 gPV(DIM / BN, NTOK / BM);     // (4, 32)
    gemm_1p<3><<<gPV, blk, SMEM_G>>>(Ps, Vt, NTOK, NTOK, NTOK, DIM,
                                     out, nullptr, nullptr, Rsum);
}